// round 1
// baseline (speedup 1.0000x reference)
#include <cuda_runtime.h>
#include <cstddef>

// Problem constants
#define Bsz 16
#define Ssz 512
#define Nent 64
#define Hdim 768
#define HH 384          // H/2
#define ET 9
#define RT 10
#define NPAIR 2016      // 64*63/2
#define MS (Bsz*Ssz)    // 8192
#define ME (Bsz*Nent)   // 1024

// Scratch (static device arrays — allocation-free rule)
__device__ float g_hidden[(size_t)MS * HH];   // relu(seq@W1e+b1e)  12.6 MB
__device__ float g_pA[(size_t)ME * Hdim];     // er@W1r_top + b1r    3.1 MB
__device__ float g_pB[(size_t)ME * Hdim];     // er@W1r_bot          3.1 MB
__device__ int   g_pairs[NPAIR * 2];

// ---------------------------------------------------------------------------
// Tiled SGEMM: C[M,N] = op(A[M,K] @ B[K,N] + bias), row-major, fp32.
// BM=128, BN=64, BK=16, 256 threads, 8x4 microtile.
// Requires M%128==0, N%64==0, K%16==0 (true for all call sites).
// ---------------------------------------------------------------------------
#define BM 128
#define BN 64
#define BK 16

template<bool RELU, bool HASBIAS>
__global__ __launch_bounds__(256) void sgemm_kernel(
    const float* __restrict__ A, const float* __restrict__ B,
    const float* __restrict__ bias, float* __restrict__ C,
    int M, int N, int K)
{
    __shared__ float As[BK][BM];   // transposed A tile
    __shared__ float Bs[BK][BN];

    const int tid = threadIdx.x;
    const int tx = tid & 15;       // 0..15 -> N
    const int ty = tid >> 4;       // 0..15 -> M
    const int bm = blockIdx.y * BM;
    const int bn = blockIdx.x * BN;

    float acc[8][4];
#pragma unroll
    for (int r = 0; r < 8; r++)
#pragma unroll
        for (int c = 0; c < 4; c++) acc[r][c] = 0.f;

    const float* Aptr = A + (size_t)bm * K;
    const float* Bptr = B + bn;

    for (int k0 = 0; k0 < K; k0 += BK) {
        // Load A tile: 128x16 = 512 float4, 2 per thread, store transposed
#pragma unroll
        for (int q = 0; q < 2; q++) {
            int idx = q * 256 + tid;
            int row = idx >> 2;            // 0..127
            int kc  = (idx & 3) << 2;      // 0,4,8,12
            float4 v = *(const float4*)(Aptr + (size_t)row * K + k0 + kc);
            As[kc + 0][row] = v.x;
            As[kc + 1][row] = v.y;
            As[kc + 2][row] = v.z;
            As[kc + 3][row] = v.w;
        }
        // Load B tile: 16x64 = 256 float4, 1 per thread
        {
            int brow = tid >> 4;           // 0..15
            int bcol = (tid & 15) << 2;    // 0..60
            float4 v = *(const float4*)(Bptr + (size_t)(k0 + brow) * N + bcol);
            *(float4*)&Bs[brow][bcol] = v;
        }
        __syncthreads();

#pragma unroll
        for (int k = 0; k < BK; k++) {
            float4 a0 = *(const float4*)&As[k][ty * 8];
            float4 a1 = *(const float4*)&As[k][ty * 8 + 4];
            float4 b0 = *(const float4*)&Bs[k][tx * 4];
            float am[8] = {a0.x, a0.y, a0.z, a0.w, a1.x, a1.y, a1.z, a1.w};
            float bv[4] = {b0.x, b0.y, b0.z, b0.w};
#pragma unroll
            for (int r = 0; r < 8; r++)
#pragma unroll
                for (int c = 0; c < 4; c++)
                    acc[r][c] += am[r] * bv[c];
        }
        __syncthreads();
    }

    // Epilogue
    const int col = bn + tx * 4;
    float bv[4] = {0.f, 0.f, 0.f, 0.f};
    if (HASBIAS) {
        float4 t = *(const float4*)(bias + col);
        bv[0] = t.x; bv[1] = t.y; bv[2] = t.z; bv[3] = t.w;
    }
#pragma unroll
    for (int r = 0; r < 8; r++) {
        int row = bm + ty * 8 + r;
        float4 v;
        v.x = acc[r][0] + bv[0];
        v.y = acc[r][1] + bv[1];
        v.z = acc[r][2] + bv[2];
        v.w = acc[r][3] + bv[3];
        if (RELU) {
            v.x = fmaxf(v.x, 0.f); v.y = fmaxf(v.y, 0.f);
            v.z = fmaxf(v.z, 0.f); v.w = fmaxf(v.w, 0.f);
        }
        *(float4*)(C + (size_t)row * N + col) = v;
    }
}

// ---------------------------------------------------------------------------
// entity_logits = hidden[8192,384] @ W2e[384,9] + b2e. Warp per row.
// ---------------------------------------------------------------------------
__global__ __launch_bounds__(256) void entity_logits_kernel(
    const float* __restrict__ hidden, const float* __restrict__ W2e,
    const float* __restrict__ b2e, float* __restrict__ out)
{
    __shared__ float W2s[HH * ET];   // 13.8 KB
    const int tid = threadIdx.x;
    for (int i = tid; i < HH * ET; i += 256) W2s[i] = W2e[i];
    __syncthreads();

    const int warp = tid >> 5, lane = tid & 31;
    const int row = blockIdx.x * 8 + warp;   // 8192 rows
    const float* hrow = hidden + (size_t)row * HH;

    float acc[ET];
#pragma unroll
    for (int c = 0; c < ET; c++) acc[c] = 0.f;

#pragma unroll
    for (int kk = 0; kk < HH / 32; kk++) {
        int k = kk * 32 + lane;
        float h = hrow[k];
        const float* w = &W2s[k * ET];
#pragma unroll
        for (int c = 0; c < ET; c++) acc[c] += h * w[c];
    }
#pragma unroll
    for (int c = 0; c < ET; c++)
#pragma unroll
        for (int off = 16; off > 0; off >>= 1)
            acc[c] += __shfl_down_sync(0xffffffffu, acc[c], off);

    if (lane == 0) {
        float* o = out + (size_t)row * ET;
#pragma unroll
        for (int c = 0; c < ET; c++) o[c] = acc[c] + b2e[c];
    }
}

// ---------------------------------------------------------------------------
// Span mean pooling: entity_repr[b,n,:] = mean(seq[b, start:end, :]). Block per (b,n).
// ---------------------------------------------------------------------------
__global__ __launch_bounds__(256) void span_pool_kernel(
    const float* __restrict__ seq, const int* __restrict__ spans,
    float* __restrict__ er)
{
    const int bn = blockIdx.x;           // 0..1023
    const int b = bn >> 6;
    const int s0 = spans[bn * 2];
    const int s1 = spans[bn * 2 + 1];
    int cnt = s1 - s0; if (cnt < 1) cnt = 1;
    const float inv = 1.f / (float)cnt;
    const float* base = seq + (size_t)b * Ssz * Hdim;

    for (int h = threadIdx.x; h < Hdim; h += 256) {
        float sum = 0.f;
        for (int s = s0; s < s1; s++) sum += base[(size_t)s * Hdim + h];
        er[(size_t)bn * Hdim + h] = sum * inv;
    }
}

// ---------------------------------------------------------------------------
// Pair index table: p -> (i, j), triu(k=1) row-major ordering.
// ---------------------------------------------------------------------------
__global__ void pair_table_kernel()
{
    int p = blockIdx.x * blockDim.x + threadIdx.x;
    if (p >= NPAIR) return;
    int rem = p, i = 0;
    while (rem >= (Nent - 1) - i) { rem -= (Nent - 1) - i; i++; }
    g_pairs[p * 2]     = i;
    g_pairs[p * 2 + 1] = i + 1 + rem;
}

// ---------------------------------------------------------------------------
// relation_logits[b,p,:] = relu(g_pA[b,i] + g_pB[b,j]) @ W2r + b2r. Warp per pair.
// W2r held in smem padded to 12 floats/row (16B-aligned float4 loads).
// ---------------------------------------------------------------------------
__global__ __launch_bounds__(256) void relation_kernel(
    const float* __restrict__ W2r, const float* __restrict__ b2r,
    float* __restrict__ out)
{
    __shared__ float W2s[Hdim * 12];   // 36.9 KB
    const int tid = threadIdx.x;
    for (int idx = tid; idx < Hdim * 12; idx += 256) {
        int k = idx / 12, c = idx % 12;
        W2s[idx] = (c < RT) ? W2r[k * RT + c] : 0.f;
    }
    __syncthreads();

    const int warp = tid >> 5, lane = tid & 31;
    const int gw = blockIdx.x * 8 + warp;    // 0..32255
    const int b = gw / NPAIR;
    const int p = gw - b * NPAIR;
    const int i = g_pairs[p * 2];
    const int j = g_pairs[p * 2 + 1];
    const float* rowA = g_pA + (size_t)(b * Nent + i) * Hdim;
    const float* rowB = g_pB + (size_t)(b * Nent + j) * Hdim;

    float acc[12];
#pragma unroll
    for (int c = 0; c < 12; c++) acc[c] = 0.f;

#pragma unroll
    for (int kk = 0; kk < Hdim / 32; kk++) {
        int k = kk * 32 + lane;
        float h = fmaxf(rowA[k] + rowB[k], 0.f);
        const float4* w = (const float4*)&W2s[k * 12];
        float4 w0 = w[0], w1 = w[1], w2 = w[2];
        acc[0] += h * w0.x; acc[1] += h * w0.y; acc[2] += h * w0.z; acc[3] += h * w0.w;
        acc[4] += h * w1.x; acc[5] += h * w1.y; acc[6] += h * w1.z; acc[7] += h * w1.w;
        acc[8] += h * w2.x; acc[9] += h * w2.y;
    }
#pragma unroll
    for (int c = 0; c < RT; c++)
#pragma unroll
        for (int off = 16; off > 0; off >>= 1)
            acc[c] += __shfl_down_sync(0xffffffffu, acc[c], off);

    if (lane == 0) {
        float* o = out + (size_t)(b * NPAIR + p) * RT;
#pragma unroll
        for (int c = 0; c < RT; c++) o[c] = acc[c] + b2r[c];
    }
}

// ---------------------------------------------------------------------------
extern "C" void kernel_launch(void* const* d_in, const int* in_sizes, int n_in,
                              void* d_out, int out_size)
{
    const float* seq   = (const float*)d_in[0];
    // d_in[1] = attention_mask (unused by the reference math)
    const int*   spans = (const int*)d_in[2];
    const float* W1e   = (const float*)d_in[3];
    const float* b1e   = (const float*)d_in[4];
    const float* W2e   = (const float*)d_in[5];
    const float* b2e   = (const float*)d_in[6];
    const float* W1r   = (const float*)d_in[7];
    const float* b1r   = (const float*)d_in[8];
    const float* W2r   = (const float*)d_in[9];
    const float* b2r   = (const float*)d_in[10];

    float* out = (float*)d_out;
    float* EL = out;                                   // [16,512,9]
    float* ER = out + (size_t)MS * ET;                 // [16,64,768]
    float* RL = ER + (size_t)ME * Hdim;                // [16,2016,10]

    void *p_hidden, *p_pA, *p_pB;
    cudaGetSymbolAddress(&p_hidden, g_hidden);
    cudaGetSymbolAddress(&p_pA, g_pA);
    cudaGetSymbolAddress(&p_pB, g_pB);
    float* hidden = (float*)p_hidden;
    float* pA = (float*)p_pA;
    float* pB = (float*)p_pB;

    // Pair table (recomputed every call; deterministic)
    pair_table_kernel<<<(NPAIR + 255) / 256, 256>>>();

    // hidden = relu(seq @ W1e + b1e)   [8192,384]
    sgemm_kernel<true, true><<<dim3(HH / BN, MS / BM), 256>>>(
        seq, W1e, b1e, hidden, MS, HH, Hdim);

    // entity_logits = hidden @ W2e + b2e
    entity_logits_kernel<<<MS / 8, 256>>>(hidden, W2e, b2e, EL);

    // entity_repr (also an output)
    span_pool_kernel<<<Bsz * Nent, 256>>>(seq, spans, ER);

    // pA = er @ W1r[:768] + b1r ; pB = er @ W1r[768:]
    sgemm_kernel<false, true><<<dim3(Hdim / BN, ME / BM), 256>>>(
        ER, W1r, b1r, pA, ME, Hdim, Hdim);
    sgemm_kernel<false, false><<<dim3(Hdim / BN, ME / BM), 256>>>(
        ER, W1r + (size_t)Hdim * Hdim, nullptr, pB, ME, Hdim, Hdim);

    // relation_logits
    relation_kernel<<<(Bsz * NPAIR) / 8, 256>>>(W2r, b2r, RL);
}

// round 3
// speedup vs baseline: 1.3263x; 1.3263x over previous
#include <cuda_runtime.h>
#include <cstdint>
#include <cstddef>

// Problem constants
#define Bsz 16
#define Ssz 512
#define Nent 64
#define Hdim 768
#define HH 384          // H/2
#define ET 9
#define RT 10
#define NPAIR 2016      // 64*63/2
#define MS (Bsz*Ssz)    // 8192
#define ME (Bsz*Nent)   // 1024
#define PAIRN (2*Hdim)  // 1536

// Scratch (static device arrays — allocation-free rule)
__device__ float g_hidden[(size_t)MS * HH];            // relu(seq@W1e+b1e)
__device__ float g_Bcat[(size_t)Hdim * PAIRN];         // [W1r_top | W1r_bot] as [768,1536]
__device__ float g_pK[2][(size_t)ME * PAIRN];          // split-K partials
__device__ float g_pAB[(size_t)ME * PAIRN];            // combined [pA | pB]
__device__ int   g_pairs[NPAIR * 2];

// ===========================================================================
// Packed fp32x2 helpers (base sm_100-family PTX, compiles for compute_103)
// ===========================================================================
__device__ __forceinline__ void ffma2(unsigned long long& d,
                                      unsigned long long a,
                                      unsigned long long b) {
    asm("fma.rn.f32x2 %0, %1, %2, %0;" : "+l"(d) : "l"(a), "l"(b));
}
__device__ __forceinline__ unsigned long long dup2(float x) {
    unsigned long long r; unsigned u = __float_as_uint(x);
    asm("mov.b64 %0, {%1, %1};" : "=l"(r) : "r"(u));
    return r;
}
__device__ __forceinline__ float2 unpack2(unsigned long long v) {
    unsigned lo, hi;
    asm("mov.b64 {%0, %1}, %2;" : "=r"(lo), "=r"(hi) : "l"(v));
    return make_float2(__uint_as_float(lo), __uint_as_float(hi));
}

// ===========================================================================
// FFMA2 SGEMM: C[M,N] = op(A[M,K] @ B[K,N] + bias), row-major fp32.
// CTA tile 64x128, BK=16, 128 threads, 8x8 microtile (4 col-pair accs/row).
// gridDim = (N/128, M/64, SPLITZ); z splits K (each z does Kper, writes its
// own C plane at C + z*zCoff). Requires M%64==0, N%128==0, Kper%16==0.
// ===========================================================================
#define GTM 64
#define GTN 128
#define GTK 16

template<bool RELU, bool HASBIAS>
__global__ __launch_bounds__(128) void gemm_f2(
    const float* __restrict__ A, int lda,
    const float* __restrict__ B, int ldb,
    const float* __restrict__ bias,
    float* __restrict__ C, int ldc,
    int Kper, size_t zCoff)
{
    __shared__ float As[2][GTK][68];     // padded: k-stride 68 floats
    __shared__ float Bs[2][GTK][GTN];

    const int tid = threadIdx.x;
    const int wid = tid >> 5, lane = tid & 31;
    const int lane_m = lane >> 2;        // 0..7
    const int lane_n = lane & 3;         // 0..3
    const int row0 = lane_m * 8;         // 0..56
    const int col0 = wid * 32 + lane_n * 8;

    const int bm = blockIdx.y * GTM;
    const int bn = blockIdx.x * GTN;
    const int z = blockIdx.z;

    const float* Ab = A + (size_t)z * Kper;              // K offset along rows
    const float* Bb = B + (size_t)z * Kper * ldb;        // K offset along rows of B
    float* Cb = C + (size_t)z * zCoff;

    unsigned long long acc[8][4];
#pragma unroll
    for (int r = 0; r < 8; r++)
#pragma unroll
        for (int c = 0; c < 4; c++) acc[r][c] = 0ull;

    const int CH = Kper / GTK;

    // global-load register buffers
    float4 ra[2], rb[4];

    // A tile: 64x16 = 256 float4, 2/thread. m = idx>>2, kq = (idx&3)*4
    // B tile: 16x128 = 512 float4, 4/thread. k = idx>>5, c4 = (idx&31)*4
#define LOAD_CHUNK(k0) do { \
    _Pragma("unroll") \
    for (int q = 0; q < 2; q++) { \
        int idx = q * 128 + tid; \
        int m = idx >> 2, kq = (idx & 3) << 2; \
        ra[q] = *(const float4*)(Ab + (size_t)(bm + m) * lda + (k0) + kq); \
    } \
    _Pragma("unroll") \
    for (int q = 0; q < 4; q++) { \
        int idx = q * 128 + tid; \
        int k = idx >> 5, c4 = (idx & 31) << 2; \
        rb[q] = *(const float4*)(Bb + (size_t)((k0) + k) * ldb + bn + c4); \
    } \
} while (0)

#define STS_CHUNK(st) do { \
    _Pragma("unroll") \
    for (int q = 0; q < 2; q++) { \
        int idx = q * 128 + tid; \
        int m = idx >> 2, kq = (idx & 3) << 2; \
        As[st][kq + 0][m] = ra[q].x; \
        As[st][kq + 1][m] = ra[q].y; \
        As[st][kq + 2][m] = ra[q].z; \
        As[st][kq + 3][m] = ra[q].w; \
    } \
    _Pragma("unroll") \
    for (int q = 0; q < 4; q++) { \
        int idx = q * 128 + tid; \
        int k = idx >> 5, c4 = (idx & 31) << 2; \
        *(float4*)&Bs[st][k][c4] = rb[q]; \
    } \
} while (0)

    LOAD_CHUNK(0);

    for (int c = 0; c < CH; c++) {
        const int st = c & 1;
        STS_CHUNK(st);
        __syncthreads();
        if (c + 1 < CH) LOAD_CHUNK((c + 1) * GTK);

#pragma unroll
        for (int k = 0; k < GTK; k++) {
            float4 a0 = *(const float4*)&As[st][k][row0];
            float4 a1 = *(const float4*)&As[st][k][row0 + 4];
            ulonglong2 b0 = *(const ulonglong2*)&Bs[st][k][col0];
            ulonglong2 b1 = *(const ulonglong2*)&Bs[st][k][col0 + 4];
            float av[8] = {a0.x, a0.y, a0.z, a0.w, a1.x, a1.y, a1.z, a1.w};
#pragma unroll
            for (int r = 0; r < 8; r++) {
                unsigned long long ad = dup2(av[r]);
                ffma2(acc[r][0], ad, b0.x);
                ffma2(acc[r][1], ad, b0.y);
                ffma2(acc[r][2], ad, b1.x);
                ffma2(acc[r][3], ad, b1.y);
            }
        }
        __syncthreads();  // before next STS overwrites this stage's sibling
    }

    // Epilogue
    const int colg = bn + col0;
    float bb[8] = {0, 0, 0, 0, 0, 0, 0, 0};
    if (HASBIAS) {
        float4 t0 = *(const float4*)(bias + colg);
        float4 t1 = *(const float4*)(bias + colg + 4);
        bb[0] = t0.x; bb[1] = t0.y; bb[2] = t0.z; bb[3] = t0.w;
        bb[4] = t1.x; bb[5] = t1.y; bb[6] = t1.z; bb[7] = t1.w;
    }
#pragma unroll
    for (int r = 0; r < 8; r++) {
        float o[8];
#pragma unroll
        for (int cp = 0; cp < 4; cp++) {
            float2 v = unpack2(acc[r][cp]);
            o[cp * 2]     = v.x + bb[cp * 2];
            o[cp * 2 + 1] = v.y + bb[cp * 2 + 1];
        }
        if (RELU) {
#pragma unroll
            for (int q = 0; q < 8; q++) o[q] = fmaxf(o[q], 0.f);
        }
        float* Crow = Cb + (size_t)(bm + row0 + r) * ldc + colg;
        *(float4*)Crow = make_float4(o[0], o[1], o[2], o[3]);
        *(float4*)(Crow + 4) = make_float4(o[4], o[5], o[6], o[7]);
    }
#undef LOAD_CHUNK
#undef STS_CHUNK
}

// ===========================================================================
// Prep 1: Bcat[k][j] = j<768 ? W1r[k][j] : W1r[768+k][j-768]   (float4 copy)
// ===========================================================================
__global__ __launch_bounds__(256) void prep_bcat_kernel(const float* __restrict__ W1r)
{
    int idx = blockIdx.x * 256 + threadIdx.x;             // per float4
    if (idx >= Hdim * PAIRN / 4) return;
    int k = idx / (PAIRN / 4);
    int j = (idx % (PAIRN / 4)) * 4;
    float4 v = (j < Hdim)
        ? *(const float4*)(W1r + (size_t)k * Hdim + j)
        : *(const float4*)(W1r + (size_t)(Hdim + k) * Hdim + (j - Hdim));
    *(float4*)(g_Bcat + (size_t)k * PAIRN + j) = v;
}

// Prep 2: pair index table
__global__ void prep_pairs_kernel()
{
    int p = blockIdx.x * blockDim.x + threadIdx.x;
    if (p >= NPAIR) return;
    int rem = p, i = 0;
    while (rem >= (Nent - 1) - i) { rem -= (Nent - 1) - i; i++; }
    g_pairs[p * 2]     = i;
    g_pairs[p * 2 + 1] = i + 1 + rem;
}

// ===========================================================================
// Combine split-K partials + bias: pAB = pK[0] + pK[1] + [b1r | 0]
// ===========================================================================
__global__ __launch_bounds__(256) void combine_kernel(const float* __restrict__ b1r)
{
    int idx = blockIdx.x * 256 + threadIdx.x;             // per float4
    if (idx >= ME * PAIRN / 4) return;
    int col = (idx % (PAIRN / 4)) * 4;
    float4 a = *(const float4*)(g_pK[0] + (size_t)idx * 4);
    float4 b = *(const float4*)(g_pK[1] + (size_t)idx * 4);
    float4 v = make_float4(a.x + b.x, a.y + b.y, a.z + b.z, a.w + b.w);
    if (col < Hdim) {
        float4 t = *(const float4*)(b1r + col);
        v.x += t.x; v.y += t.y; v.z += t.z; v.w += t.w;
    }
    *(float4*)(g_pAB + (size_t)idx * 4) = v;
}

// ===========================================================================
// entity_logits = hidden[8192,384] @ W2e[384,9] + b2e. Warp per row.
// ===========================================================================
__global__ __launch_bounds__(256) void entity_logits_kernel(
    const float* __restrict__ hidden, const float* __restrict__ W2e,
    const float* __restrict__ b2e, float* __restrict__ out)
{
    __shared__ float W2s[HH * ET];
    const int tid = threadIdx.x;
    for (int i = tid; i < HH * ET; i += 256) W2s[i] = W2e[i];
    __syncthreads();

    const int warp = tid >> 5, lane = tid & 31;
    const int row = blockIdx.x * 8 + warp;
    const float* hrow = hidden + (size_t)row * HH;

    float acc[ET];
#pragma unroll
    for (int c = 0; c < ET; c++) acc[c] = 0.f;

#pragma unroll
    for (int kk = 0; kk < HH / 32; kk++) {
        int k = kk * 32 + lane;
        float h = hrow[k];
        const float* w = &W2s[k * ET];
#pragma unroll
        for (int c = 0; c < ET; c++) acc[c] += h * w[c];
    }
#pragma unroll
    for (int c = 0; c < ET; c++)
#pragma unroll
        for (int off = 16; off > 0; off >>= 1)
            acc[c] += __shfl_down_sync(0xffffffffu, acc[c], off);

    if (lane == 0) {
        float* o = out + (size_t)row * ET;
#pragma unroll
        for (int c = 0; c < ET; c++) o[c] = acc[c] + b2e[c];
    }
}

// ===========================================================================
// Span mean pooling, fixed 16-iteration predicated loop (MLP=16).
// entity_repr[b,n,:] = mean(seq[b, s0:s1, :])
// ===========================================================================
__global__ __launch_bounds__(192) void span_pool_kernel(
    const float4* __restrict__ seq4, const int* __restrict__ spans,
    float4* __restrict__ er4)
{
    const int bn = blockIdx.x;
    const int b = bn >> 6;
    const int s0 = spans[bn * 2];
    const int s1 = spans[bn * 2 + 1];
    int cnt = s1 - s0; if (cnt < 1) cnt = 1;
    const float inv = 1.f / (float)cnt;
    const float4* base = seq4 + (size_t)b * Ssz * (Hdim / 4) + threadIdx.x;

    float4 acc = make_float4(0.f, 0.f, 0.f, 0.f);
#pragma unroll
    for (int q = 0; q < 16; q++) {
        int s = s0 + q;
        float4 v = base[(size_t)s * (Hdim / 4)];   // always in-bounds: s0 < S-16
        if (s < s1) { acc.x += v.x; acc.y += v.y; acc.z += v.z; acc.w += v.w; }
    }
    acc.x *= inv; acc.y *= inv; acc.z *= inv; acc.w *= inv;
    er4[(size_t)bn * (Hdim / 4) + threadIdx.x] = acc;
}

// ===========================================================================
// relation_logits[b,p,:] = relu(pAB[b,i][0:768] + pAB[b,j][768:1536]) @ W2r + b2r
// ===========================================================================
__global__ __launch_bounds__(256) void relation_kernel(
    const float* __restrict__ W2r, const float* __restrict__ b2r,
    float* __restrict__ out)
{
    __shared__ __align__(16) float W2s[Hdim * 12];
    const int tid = threadIdx.x;
    for (int idx = tid; idx < Hdim * 12; idx += 256) {
        int k = idx / 12, c = idx % 12;
        W2s[idx] = (c < RT) ? W2r[k * RT + c] : 0.f;
    }
    __syncthreads();

    const int warp = tid >> 5, lane = tid & 31;
    const int gw = blockIdx.x * 8 + warp;
    const int b = gw / NPAIR;
    const int p = gw - b * NPAIR;
    const int i = g_pairs[p * 2];
    const int j = g_pairs[p * 2 + 1];
    const float* rowA = g_pAB + (size_t)(b * Nent + i) * PAIRN;
    const float* rowB = g_pAB + (size_t)(b * Nent + j) * PAIRN + Hdim;

    float acc[12];
#pragma unroll
    for (int c = 0; c < 12; c++) acc[c] = 0.f;

#pragma unroll
    for (int kk = 0; kk < Hdim / 32; kk++) {
        int k = kk * 32 + lane;
        float h = fmaxf(rowA[k] + rowB[k], 0.f);
        const float4* w = (const float4*)&W2s[k * 12];
        float4 w0 = w[0], w1 = w[1], w2 = w[2];
        acc[0] += h * w0.x; acc[1] += h * w0.y; acc[2] += h * w0.z; acc[3] += h * w0.w;
        acc[4] += h * w1.x; acc[5] += h * w1.y; acc[6] += h * w1.z; acc[7] += h * w1.w;
        acc[8] += h * w2.x; acc[9] += h * w2.y;
    }
#pragma unroll
    for (int c = 0; c < RT; c++)
#pragma unroll
        for (int off = 16; off > 0; off >>= 1)
            acc[c] += __shfl_down_sync(0xffffffffu, acc[c], off);

    if (lane == 0) {
        float* o = out + (size_t)(b * NPAIR + p) * RT;
#pragma unroll
        for (int c = 0; c < RT; c++) o[c] = acc[c] + b2r[c];
    }
}

// ===========================================================================
extern "C" void kernel_launch(void* const* d_in, const int* in_sizes, int n_in,
                              void* d_out, int out_size)
{
    const float* seq   = (const float*)d_in[0];
    const int*   spans = (const int*)d_in[2];
    const float* W1e   = (const float*)d_in[3];
    const float* b1e   = (const float*)d_in[4];
    const float* W2e   = (const float*)d_in[5];
    const float* b2e   = (const float*)d_in[6];
    const float* W1r   = (const float*)d_in[7];
    const float* b1r   = (const float*)d_in[8];
    const float* W2r   = (const float*)d_in[9];
    const float* b2r   = (const float*)d_in[10];

    float* out = (float*)d_out;
    float* EL = out;                                   // [16,512,9]
    float* ER = out + (size_t)MS * ET;                 // [16,64,768]
    float* RL = ER + (size_t)ME * Hdim;                // [16,2016,10]

    void *p_hidden, *p_Bcat, *p_pK;
    cudaGetSymbolAddress(&p_hidden, g_hidden);
    cudaGetSymbolAddress(&p_Bcat, g_Bcat);
    cudaGetSymbolAddress(&p_pK, g_pK);
    float* hidden = (float*)p_hidden;

    // Prep (independent of everything downstream)
    prep_bcat_kernel<<<(Hdim * PAIRN / 4 + 255) / 256, 256>>>(W1r);
    prep_pairs_kernel<<<(NPAIR + 255) / 256, 256>>>();

    // entity_repr (output; input of pair GEMM)
    span_pool_kernel<<<Bsz * Nent, 192>>>((const float4*)seq, spans, (float4*)ER);

    // hidden = relu(seq @ W1e + b1e)   [8192,384]
    gemm_f2<true, true><<<dim3(HH / GTN, MS / GTM, 1), 128>>>(
        seq, Hdim, W1e, HH, b1e, hidden, HH, Hdim, 0);

    // entity_logits = hidden @ W2e + b2e
    entity_logits_kernel<<<MS / 8, 256>>>(hidden, W2e, b2e, EL);

    // pK[z] = ER @ Bcat[zK:(z+1)K, :]   split-K=2, one launch, 384 CTAs
    gemm_f2<false, false><<<dim3(PAIRN / GTN, ME / GTM, 2), 128>>>(
        ER, Hdim, (const float*)p_Bcat, PAIRN, nullptr,
        (float*)p_pK, PAIRN, Hdim / 2, (size_t)ME * PAIRN);

    // pAB = pK[0] + pK[1] + [b1r | 0]
    combine_kernel<<<(ME * PAIRN / 4 + 255) / 256, 256>>>(b1r);

    // relation_logits
    relation_kernel<<<(Bsz * NPAIR) / 8, 256>>>(W2r, b2r, RL);
}

// round 4
// speedup vs baseline: 1.3625x; 1.0273x over previous
#include <cuda_runtime.h>
#include <cstdint>
#include <cstddef>

// Problem constants
#define Bsz 16
#define Ssz 512
#define Nent 64
#define Hdim 768
#define HH 384          // H/2
#define ET 9
#define RT 10
#define NPAIR 2016      // 64*63/2
#define MS (Bsz*Ssz)    // 8192
#define ME (Bsz*Nent)   // 1024
#define PAIRN (2*Hdim)  // 1536

// Scratch (static device arrays — allocation-free rule)
__device__ float g_hidden[(size_t)MS * HH];            // relu(seq@W1e+b1e)
__device__ float g_Bcat[(size_t)Hdim * PAIRN];         // [W1r_top | W1r_bot] as [768,1536]
__device__ float g_pK[2][(size_t)ME * PAIRN];          // split-K partials
__device__ float g_pAT[(size_t)Bsz * Hdim * Nent];     // pA transposed [b][k][n]
__device__ float g_pBT[(size_t)Bsz * Hdim * Nent];     // pB transposed [b][k][n]
__device__ int   g_pairs[NPAIR * 2];

// ===========================================================================
// Packed fp32x2 + cp.async helpers (base-ISA PTX, compiles for compute_103)
// ===========================================================================
__device__ __forceinline__ void ffma2(unsigned long long& d,
                                      unsigned long long a,
                                      unsigned long long b) {
    asm("fma.rn.f32x2 %0, %1, %2, %0;" : "+l"(d) : "l"(a), "l"(b));
}
__device__ __forceinline__ unsigned long long dup2(float x) {
    unsigned long long r; unsigned u = __float_as_uint(x);
    asm("mov.b64 %0, {%1, %1};" : "=l"(r) : "r"(u));
    return r;
}
__device__ __forceinline__ float2 unpack2(unsigned long long v) {
    unsigned lo, hi;
    asm("mov.b64 {%0, %1}, %2;" : "=r"(lo), "=r"(hi) : "l"(v));
    return make_float2(__uint_as_float(lo), __uint_as_float(hi));
}
__device__ __forceinline__ uint32_t smem_u32(const void* p) {
    uint32_t a;
    asm("{ .reg .u64 t; cvta.to.shared.u64 t, %1; cvt.u32.u64 %0, t; }"
        : "=r"(a) : "l"(p));
    return a;
}
__device__ __forceinline__ void cp_async16(uint32_t saddr, const void* gaddr) {
    asm volatile("cp.async.cg.shared.global [%0], [%1], 16;"
                 :: "r"(saddr), "l"(gaddr) : "memory");
}
#define CP_COMMIT() asm volatile("cp.async.commit_group;" ::: "memory")
#define CP_WAIT0()  asm volatile("cp.async.wait_group 0;" ::: "memory")

// ===========================================================================
// FFMA2 SGEMM: C = op(A[M,K] @ B[K,N] + bias), row-major fp32.
// CTA tile 64x128, BK=32, 128 threads, microtile rows {4lm+j}∪{32+4lm+j} x 8 cols.
// A transposed+swizzled in smem (register-staged), B via cp.async raw.
// gridDim = (N/128, M/64, SPLITZ); z splits K, writes plane C + z*zCoff.
// ===========================================================================
#define GTM 64
#define GTN 128
#define GTK 32
#define ASTRIDE 68                     // words per k-row of A smem
#define ASTAGE (GTK*ASTRIDE)           // 2176 floats
#define BSTAGE (GTK*GTN)               // 4096 floats
#define GEMM_SMEM ((2*ASTAGE + 2*BSTAGE) * 4)   // 50176 bytes

template<bool RELU, bool HASBIAS>
__global__ __launch_bounds__(128) void gemm_f2(
    const float* __restrict__ A, int lda,
    const float* __restrict__ B, int ldb,
    const float* __restrict__ bias,
    float* __restrict__ C, int ldc,
    int Kper, size_t zCoff)
{
    extern __shared__ float sm[];
    float* smA = sm;                   // 2 stages x ASTAGE
    float* smB = sm + 2 * ASTAGE;      // 2 stages x BSTAGE

    const int tid = threadIdx.x;
    const int wid = tid >> 5, lane = tid & 31;
    const int lm = lane >> 2;          // 0..7
    const int ln = lane & 3;           // 0..3
    const int col0 = wid * 32 + ln * 8;

    const int bm = blockIdx.y * GTM;
    const int bn = blockIdx.x * GTN;
    const int z = blockIdx.z;

    const float* Ab = A + (size_t)z * Kper;
    const float* Bb = B + (size_t)z * Kper * ldb;
    float* Cb = C + (size_t)z * zCoff;

    unsigned long long acc[4][8];      // [row-pair][col]
#pragma unroll
    for (int r = 0; r < 4; r++)
#pragma unroll
        for (int c = 0; c < 8; c++) acc[r][c] = 0ull;

    const int CH = Kper / GTK;
    float4 ra[4];

    // ---- fill helpers ----
    // A: idx = q*128+tid -> m = idx>>3 (0..63), kq = (idx&7)*4 ; coalesced LDG
#define LDG_A(k0) do { \
    _Pragma("unroll") \
    for (int q = 0; q < 4; q++) { \
        int idx = q * 128 + tid; \
        int m = idx >> 3, kq = (idx & 7) << 2; \
        ra[q] = *(const float4*)(Ab + (size_t)(bm + m) * lda + (k0) + kq); \
    } \
} while (0)
    // STS transposed + swizzle: addr(k, m) = k*68 + (m ^ (((k>>2)&7)<<2))
#define STS_A(dst) do { \
    _Pragma("unroll") \
    for (int q = 0; q < 4; q++) { \
        int idx = q * 128 + tid; \
        int m = idx >> 3, kq = (idx & 7) << 2; \
        int ms = m ^ kq;  /* ((kq+i)>>2)&7)<<2 == kq for i<4 */ \
        (dst)[(kq + 0) * ASTRIDE + ms] = ra[q].x; \
        (dst)[(kq + 1) * ASTRIDE + ms] = ra[q].y; \
        (dst)[(kq + 2) * ASTRIDE + ms] = ra[q].z; \
        (dst)[(kq + 3) * ASTRIDE + ms] = ra[q].w; \
    } \
} while (0)
    // B: idx = q*128+tid -> k = idx>>5, c4 = (idx&31)*4 ; smem offset = idx*16B
#define CPA_B(k0, stB) do { \
    uint32_t sb = smem_u32(smB + (stB) * BSTAGE) + (uint32_t)tid * 16u; \
    _Pragma("unroll") \
    for (int q = 0; q < 8; q++) { \
        int idx = q * 128 + tid; \
        int k = idx >> 5, c4 = (idx & 31) << 2; \
        cp_async16(sb + q * 2048u, Bb + (size_t)((k0) + k) * ldb + bn + c4); \
    } \
    CP_COMMIT(); \
} while (0)

    // ---- prologue: fill stage 0 ----
    CPA_B(0, 0);
    LDG_A(0);
    STS_A(smA);
    CP_WAIT0();
    __syncthreads();

    for (int c = 0; c < CH; c++) {
        const int st = c & 1;
        const int nx = st ^ 1;
        if (c + 1 < CH) {
            CPA_B((c + 1) * GTK, nx);
            LDG_A((c + 1) * GTK);
        }

        const float* Asm = smA + st * ASTAGE;
        const float* Bsm = smB + st * BSTAGE;
#pragma unroll
        for (int k = 0; k < GTK; k++) {
            const int sw = ((k >> 2) & 7) << 2;
            ulonglong2 ap0 = *(const ulonglong2*)&Asm[k * ASTRIDE + ((4 * lm) ^ sw)];
            ulonglong2 ap1 = *(const ulonglong2*)&Asm[k * ASTRIDE + (32 + ((4 * lm) ^ sw))];
            float4 b0 = *(const float4*)&Bsm[k * GTN + col0];
            float4 b1 = *(const float4*)&Bsm[k * GTN + col0 + 4];
            unsigned long long bd[8];
            bd[0] = dup2(b0.x); bd[1] = dup2(b0.y); bd[2] = dup2(b0.z); bd[3] = dup2(b0.w);
            bd[4] = dup2(b1.x); bd[5] = dup2(b1.y); bd[6] = dup2(b1.z); bd[7] = dup2(b1.w);
            unsigned long long ap[4] = {ap0.x, ap0.y, ap1.x, ap1.y};
#pragma unroll
            for (int r = 0; r < 4; r++)
#pragma unroll
                for (int cc = 0; cc < 8; cc++)
                    ffma2(acc[r][cc], ap[r], bd[cc]);
        }

        if (c + 1 < CH) STS_A(smA + nx * ASTAGE);
        CP_WAIT0();
        __syncthreads();
    }

    // ---- epilogue ----
    const int colg = bn + col0;
    float bb[8] = {0, 0, 0, 0, 0, 0, 0, 0};
    if (HASBIAS) {
        float4 t0 = *(const float4*)(bias + colg);
        float4 t1 = *(const float4*)(bias + colg + 4);
        bb[0] = t0.x; bb[1] = t0.y; bb[2] = t0.z; bb[3] = t0.w;
        bb[4] = t1.x; bb[5] = t1.y; bb[6] = t1.z; bb[7] = t1.w;
    }
#pragma unroll
    for (int rp = 0; rp < 4; rp++) {
        int r0 = (rp < 2) ? (4 * lm + 2 * rp) : (32 + 4 * lm + 2 * (rp - 2));
        float lo[8], hi[8];
#pragma unroll
        for (int cc = 0; cc < 8; cc++) {
            float2 v = unpack2(acc[rp][cc]);
            lo[cc] = v.x + bb[cc];
            hi[cc] = v.y + bb[cc];
        }
        if (RELU) {
#pragma unroll
            for (int cc = 0; cc < 8; cc++) {
                lo[cc] = fmaxf(lo[cc], 0.f);
                hi[cc] = fmaxf(hi[cc], 0.f);
            }
        }
        float* C0 = Cb + (size_t)(bm + r0) * ldc + colg;
        float* C1 = Cb + (size_t)(bm + r0 + 1) * ldc + colg;
        *(float4*)C0 = make_float4(lo[0], lo[1], lo[2], lo[3]);
        *(float4*)(C0 + 4) = make_float4(lo[4], lo[5], lo[6], lo[7]);
        *(float4*)C1 = make_float4(hi[0], hi[1], hi[2], hi[3]);
        *(float4*)(C1 + 4) = make_float4(hi[4], hi[5], hi[6], hi[7]);
    }
#undef LDG_A
#undef STS_A
#undef CPA_B
}

// ===========================================================================
// Prep 1: Bcat[k][j] = j<768 ? W1r[k][j] : W1r[768+k][j-768]
// ===========================================================================
__global__ __launch_bounds__(256) void prep_bcat_kernel(const float* __restrict__ W1r)
{
    int idx = blockIdx.x * 256 + threadIdx.x;             // per float4
    if (idx >= Hdim * PAIRN / 4) return;
    int k = idx / (PAIRN / 4);
    int j = (idx % (PAIRN / 4)) * 4;
    float4 v = (j < Hdim)
        ? *(const float4*)(W1r + (size_t)k * Hdim + j)
        : *(const float4*)(W1r + (size_t)(Hdim + k) * Hdim + (j - Hdim));
    *(float4*)(g_Bcat + (size_t)k * PAIRN + j) = v;
}

// Prep 2: pair index table
__global__ void prep_pairs_kernel()
{
    int p = blockIdx.x * blockDim.x + threadIdx.x;
    if (p >= NPAIR) return;
    int rem = p, i = 0;
    while (rem >= (Nent - 1) - i) { rem -= (Nent - 1) - i; i++; }
    g_pairs[p * 2]     = i;
    g_pairs[p * 2 + 1] = i + 1 + rem;
}

// ===========================================================================
// Combine split-K + bias + transpose:
//  in:  pK[0]+pK[1] at [e=(b,n)][k'] (k'<768 -> pA + b1r, else pB)
//  out: pAT[b][k][n], pBT[b][k][n]
// ===========================================================================
__global__ __launch_bounds__(256) void combine_transpose_kernel(
    const float* __restrict__ b1r)
{
    __shared__ float t[32][33];
    const int kb = blockIdx.x * 32;        // k' base 0..1535
    const int eb = blockIdx.y * 32;        // entity-row base 0..1023
    const int tx = threadIdx.x & 31;
    const int ty = threadIdx.x >> 5;       // 0..7

#pragma unroll
    for (int s = 0; s < 4; s++) {
        int e = eb + ty + s * 8;
        size_t off = (size_t)e * PAIRN + kb + tx;
        t[ty + s * 8][tx] = g_pK[0][off] + g_pK[1][off];
    }
    __syncthreads();

    const int b = eb >> 6;
    const int n0 = eb & 63;
#pragma unroll
    for (int s = 0; s < 4; s++) {
        int kk = kb + ty + s * 8;
        float v = t[tx][ty + s * 8];
        if (kk < Hdim) {
            v += b1r[kk];
            g_pAT[((size_t)b * Hdim + kk) * Nent + n0 + tx] = v;
        } else {
            g_pBT[((size_t)b * Hdim + (kk - Hdim)) * Nent + n0 + tx] = v;
        }
    }
}

// ===========================================================================
// entity_logits = hidden[8192,384] @ W2e[384,9] + b2e. Warp per row.
// ===========================================================================
__global__ __launch_bounds__(256) void entity_logits_kernel(
    const float* __restrict__ hidden, const float* __restrict__ W2e,
    const float* __restrict__ b2e, float* __restrict__ out)
{
    __shared__ float W2s[HH * ET];
    const int tid = threadIdx.x;
    for (int i = tid; i < HH * ET; i += 256) W2s[i] = W2e[i];
    __syncthreads();

    const int warp = tid >> 5, lane = tid & 31;
    const int row = blockIdx.x * 8 + warp;
    const float* hrow = hidden + (size_t)row * HH;

    float acc[ET];
#pragma unroll
    for (int c = 0; c < ET; c++) acc[c] = 0.f;

#pragma unroll
    for (int kk = 0; kk < HH / 32; kk++) {
        int k = kk * 32 + lane;
        float h = hrow[k];
        const float* w = &W2s[k * ET];
#pragma unroll
        for (int c = 0; c < ET; c++) acc[c] += h * w[c];
    }
#pragma unroll
    for (int c = 0; c < ET; c++)
#pragma unroll
        for (int off = 16; off > 0; off >>= 1)
            acc[c] += __shfl_down_sync(0xffffffffu, acc[c], off);

    if (lane == 0) {
        float* o = out + (size_t)row * ET;
#pragma unroll
        for (int c = 0; c < ET; c++) o[c] = acc[c] + b2e[c];
    }
}

// ===========================================================================
// Span mean pooling, fixed 16-iteration predicated loop.
// ===========================================================================
__global__ __launch_bounds__(192) void span_pool_kernel(
    const float4* __restrict__ seq4, const int* __restrict__ spans,
    float4* __restrict__ er4)
{
    const int bn = blockIdx.x;
    const int b = bn >> 6;
    const int s0 = spans[bn * 2];
    const int s1 = spans[bn * 2 + 1];
    int cnt = s1 - s0; if (cnt < 1) cnt = 1;
    const float inv = 1.f / (float)cnt;
    const float4* base = seq4 + (size_t)b * Ssz * (Hdim / 4) + threadIdx.x;

    float4 acc = make_float4(0.f, 0.f, 0.f, 0.f);
#pragma unroll
    for (int q = 0; q < 16; q++) {
        int s = s0 + q;
        float4 v = base[(size_t)s * (Hdim / 4)];
        if (s < s1) { acc.x += v.x; acc.y += v.y; acc.z += v.z; acc.w += v.w; }
    }
    acc.x *= inv; acc.y *= inv; acc.z *= inv; acc.w *= inv;
    er4[(size_t)bn * (Hdim / 4) + threadIdx.x] = acc;
}

// ===========================================================================
// relation_logits: thread per pair, W2 broadcast from smem, FFMA2 accs.
// h(k) = relu(pAT[b][k][i] + pBT[b][k][j]);  logits = h @ W2r + b2r
// ===========================================================================
__global__ __launch_bounds__(256) void relation_kernel(
    const float* __restrict__ W2r, const float* __restrict__ b2r,
    float* __restrict__ out)
{
    __shared__ __align__(16) float Wp[Hdim * 12];      // [k][12] padded
    const int tid = threadIdx.x;
    for (int idx = tid; idx < Hdim * 12; idx += 256) {
        int k = idx / 12, c = idx % 12;
        Wp[idx] = (c < RT) ? W2r[k * RT + c] : 0.f;
    }
    __syncthreads();

    const int b = blockIdx.y;
    const int p = blockIdx.x * 256 + tid;
    const bool act = (p < NPAIR);
    int i = 0, j = 0;
    if (act) { i = g_pairs[p * 2]; j = g_pairs[p * 2 + 1]; }

    const float* At = g_pAT + (size_t)b * Hdim * Nent;
    const float* Bt = g_pBT + (size_t)b * Hdim * Nent;

    unsigned long long acc[6];
#pragma unroll
    for (int c = 0; c < 6; c++) acc[c] = 0ull;

#pragma unroll 4
    for (int k = 0; k < Hdim; k++) {
        float h = fmaxf(At[(size_t)k * Nent + i] + Bt[(size_t)k * Nent + j], 0.f);
        unsigned long long hd = dup2(h);
        const ulonglong2* w = (const ulonglong2*)&Wp[k * 12];
        ulonglong2 w0 = w[0], w1 = w[1], w2 = w[2];
        ffma2(acc[0], hd, w0.x); ffma2(acc[1], hd, w0.y);
        ffma2(acc[2], hd, w1.x); ffma2(acc[3], hd, w1.y);
        ffma2(acc[4], hd, w2.x); ffma2(acc[5], hd, w2.y);
    }

    if (act) {
        float o[12];
#pragma unroll
        for (int c = 0; c < 6; c++) {
            float2 v = unpack2(acc[c]);
            o[c * 2] = v.x; o[c * 2 + 1] = v.y;
        }
        float* dst = out + (size_t)(b * NPAIR + p) * RT;
#pragma unroll
        for (int c = 0; c < RT; c++) dst[c] = o[c] + b2r[c];
    }
}

// ===========================================================================
extern "C" void kernel_launch(void* const* d_in, const int* in_sizes, int n_in,
                              void* d_out, int out_size)
{
    const float* seq   = (const float*)d_in[0];
    const int*   spans = (const int*)d_in[2];
    const float* W1e   = (const float*)d_in[3];
    const float* b1e   = (const float*)d_in[4];
    const float* W2e   = (const float*)d_in[5];
    const float* b2e   = (const float*)d_in[6];
    const float* W1r   = (const float*)d_in[7];
    const float* b1r   = (const float*)d_in[8];
    const float* W2r   = (const float*)d_in[9];
    const float* b2r   = (const float*)d_in[10];

    float* out = (float*)d_out;
    float* EL = out;                                   // [16,512,9]
    float* ER = out + (size_t)MS * ET;                 // [16,64,768]
    float* RL = ER + (size_t)ME * Hdim;                // [16,2016,10]

    void *p_hidden, *p_Bcat, *p_pK;
    cudaGetSymbolAddress(&p_hidden, g_hidden);
    cudaGetSymbolAddress(&p_Bcat, g_Bcat);
    cudaGetSymbolAddress(&p_pK, g_pK);
    float* hidden = (float*)p_hidden;

    cudaFuncSetAttribute(gemm_f2<true, true>,
                         cudaFuncAttributeMaxDynamicSharedMemorySize, GEMM_SMEM);
    cudaFuncSetAttribute(gemm_f2<false, false>,
                         cudaFuncAttributeMaxDynamicSharedMemorySize, GEMM_SMEM);

    // Prep
    prep_bcat_kernel<<<(Hdim * PAIRN / 4 + 255) / 256, 256>>>(W1r);
    prep_pairs_kernel<<<(NPAIR + 255) / 256, 256>>>();

    // entity_repr (output + input of pair GEMM)
    span_pool_kernel<<<Bsz * Nent, 192>>>((const float4*)seq, spans, (float4*)ER);

    // hidden = relu(seq @ W1e + b1e)   [8192,384]
    gemm_f2<true, true><<<dim3(HH / GTN, MS / GTM, 1), 128, GEMM_SMEM>>>(
        seq, Hdim, W1e, HH, b1e, hidden, HH, Hdim, 0);

    // entity_logits = hidden @ W2e + b2e
    entity_logits_kernel<<<MS / 8, 256>>>(hidden, W2e, b2e, EL);

    // pK[z] = ER @ Bcat[zK:(z+1)K, :]   split-K=2, 384 CTAs
    gemm_f2<false, false><<<dim3(PAIRN / GTN, ME / GTM, 2), 128, GEMM_SMEM>>>(
        ER, Hdim, (const float*)p_Bcat, PAIRN, nullptr,
        (float*)p_pK, PAIRN, Hdim / 2, (size_t)ME * PAIRN);

    // pAT/pBT = transpose(pK[0] + pK[1] + [b1r | 0])
    combine_transpose_kernel<<<dim3(PAIRN / 32, ME / 32), 256>>>(b1r);

    // relation_logits
    relation_kernel<<<dim3((NPAIR + 255) / 256, Bsz), 256>>>(W2r, b2r, RL);
}